// round 7
// baseline (speedup 1.0000x reference)
#include <cuda_runtime.h>
#include <cuda_fp16.h>
#include <cuda_pipeline.h>

#define T    512
#define K    4
#define G    20000
#define EPG  3
#define B    512

#define BT     32                  // batches per block tile (= lanes)
#define NBT    (B / BT)            // 16
#define BLKG   1024                // 32 warps
#define GPB    256                 // g per chunk
#define CPS    9                   // chunks per split
#define GSPLIT (GPB * CPS)         // 2304 consecutive g per block
#define NSPLIT 9                   // 9*2304 = 20736 >= 20000; grid 144 ~= 1 wave

// SMEM layout (bytes)
#define S_H2    0                          // 131072: [t][b] uint2 fp16x4
#define S_EDGE  131072                     // 27648:  [2304][3] int
#define S_B3    158720                     // 9216:   [2304] float
#define S_W3    167936                     // 24576:  [2][768] float4 (w3 chunks)
#define S_OUT   192512                     // 32768:  out tile / feature scratch
#define SMEM_TOTAL 225280

__device__ __forceinline__ float leaky(float x) {
    return x > 0.0f ? x : 0.01f * x;
}

// Packed f32x2 FMA (Blackwell FFMA2) — bit-identical to two scalar fp32 FMAs.
__device__ __forceinline__ float2 ffma2(float2 a, float2 b, float2 c) {
    float2 d;
    asm("{\n\t"
        ".reg .b64 ra, rb, rc, rd;\n\t"
        "mov.b64 ra, {%2, %3};\n\t"
        "mov.b64 rb, {%4, %5};\n\t"
        "mov.b64 rc, {%6, %7};\n\t"
        "fma.rn.f32x2 rd, ra, rb, rc;\n\t"
        "mov.b64 {%0, %1}, rd;\n\t"
        "}"
        : "=f"(d.x), "=f"(d.y)
        : "f"(a.x), "f"(a.y), "f"(b.x), "f"(b.y), "f"(c.x), "f"(c.y));
    return d;
}

__global__ void __launch_bounds__(BLKG, 1)
fused_kernel(const float*  __restrict__ features,
             const float4* __restrict__ w1,
             const float4* __restrict__ b1,
             const float4* __restrict__ w2,
             const float4* __restrict__ b2,
             const float*  __restrict__ w3,
             const float*  __restrict__ b3,
             const int*    __restrict__ edge,
             float*        __restrict__ out) {
    extern __shared__ char sm[];
    uint2*  s_h2   = reinterpret_cast<uint2*>(sm + S_H2);
    int*    s_edge = reinterpret_cast<int*>(sm + S_EDGE);
    float*  s_b3   = reinterpret_cast<float*>(sm + S_B3);
    float4* s_w3   = reinterpret_cast<float4*>(sm + S_W3);
    float*  s_out  = reinterpret_cast<float*>(sm + S_OUT);
    float4* s_f    = reinterpret_cast<float4*>(sm + S_OUT);  // scratch pre-mainloop

    const int tid   = threadIdx.x;
    const int w     = tid >> 5;
    const int lane  = tid & 31;
    const int split = blockIdx.x;
    const int bt    = blockIdx.y;
    const int g0    = split * GSPLIT;
    const int valid_g = min(GSPLIT, G - g0);   // 2304 (or 1568 on last split)

    // ---- stage edge + b3 (whole split) + w3 chunk 0, all contiguous ----
    {
        const uint4* esrc = reinterpret_cast<const uint4*>(edge + (size_t)g0 * 3);
        uint4*       edst = reinterpret_cast<uint4*>(s_edge);
        const int ne = valid_g * 3 / 4;
        for (int i = tid; i < ne; i += BLKG)
            __pipeline_memcpy_async(&edst[i], &esrc[i], 16);

        const uint4* bsrc = reinterpret_cast<const uint4*>(b3 + g0);
        uint4*       bdst = reinterpret_cast<uint4*>(s_b3);
        const int nb = valid_g / 4;
        for (int i = tid; i < nb; i += BLKG)
            __pipeline_memcpy_async(&bdst[i], &bsrc[i], 16);

        const float4* wsrc = reinterpret_cast<const float4*>(w3 + (size_t)g0 * 12);
        const int nw = GPB * 3;   // chunk 0 always fully valid (valid_g >= 1568)
        for (int i = tid; i < nw; i += BLKG)
            __pipeline_memcpy_async(&s_w3[i], &wsrc[i], 16);
    }
    __pipeline_commit();

    // ---- compute h2 tile in-block (2 halves of t, bounce via s_f scratch) ----
    {
        const int b = bt * BT + w;   // warp = batch row (coalesced feature loads)
        for (int half = 0; half < 2; half++) {
            const float4* frow =
                reinterpret_cast<const float4*>(features + (size_t)b * T + half * 256);
            const float4 fa = frow[lane];
            const float4 fb = frow[32 + lane];
            // th (t-quad within half) = j*32 + lane; xor-swizzled STS.128
            s_f[(0 * 32 + lane) * 32 + (w ^ lane)] = fa;
            s_f[(1 * 32 + lane) * 32 + (w ^ lane)] = fb;
            __syncthreads();

            #pragma unroll
            for (int it = 0; it < 2; it++) {
                const int th = w * 2 + it;                       // 0..63
                const float4 f4 = s_f[th * 32 + (lane ^ (th & 31))];
                const float fv[4] = {f4.x, f4.y, f4.z, f4.w};
                #pragma unroll
                for (int cc = 0; cc < 4; cc++) {
                    const int t = half * 256 + th * 4 + cc;
                    const float  f   = fv[cc];
                    const float4 w1v = w1[t];
                    const float4 b1v = b1[t];
                    const float4 b2v = b2[t];

                    const float h0 = leaky(fmaf(f, w1v.x, b1v.x));
                    const float h1 = leaky(fmaf(f, w1v.y, b1v.y));
                    const float h2 = leaky(fmaf(f, w1v.z, b1v.z));
                    const float h3 = leaky(fmaf(f, w1v.w, b1v.w));

                    const float4 w20 = w2[t * 4 + 0];
                    const float4 w21 = w2[t * 4 + 1];
                    const float4 w22 = w2[t * 4 + 2];
                    const float4 w23 = w2[t * 4 + 3];

                    float4 o;
                    o.x = leaky(fmaf(h3, w23.x, fmaf(h2, w22.x, fmaf(h1, w21.x, fmaf(h0, w20.x, b2v.x)))));
                    o.y = leaky(fmaf(h3, w23.y, fmaf(h2, w22.y, fmaf(h1, w21.y, fmaf(h0, w20.y, b2v.y)))));
                    o.z = leaky(fmaf(h3, w23.z, fmaf(h2, w22.z, fmaf(h1, w21.z, fmaf(h0, w20.z, b2v.z)))));
                    o.w = leaky(fmaf(h3, w23.w, fmaf(h2, w22.w, fmaf(h1, w21.w, fmaf(h0, w20.w, b2v.w)))));

                    const __half2 p0h = __floats2half2_rn(o.x, o.y);
                    const __half2 p1h = __floats2half2_rn(o.z, o.w);
                    uint2 p;
                    p.x = *reinterpret_cast<const unsigned int*>(&p0h);
                    p.y = *reinterpret_cast<const unsigned int*>(&p1h);
                    s_h2[t * 32 + lane] = p;   // lane = b: conflict-free STS.64
                }
            }
            __syncthreads();   // s_f free for next half / s_out reuse
        }
    }

    __pipeline_wait_prior(0);
    __syncthreads();

    // ---- main loop: 9 chunks of 256 g, w3 double-buffered ----
    int buf = 0;
    #pragma unroll 1
    for (int chunk = 0; chunk < CPS; chunk++) {
        const bool has_next = (chunk + 1 < CPS);
        if (has_next) {
            const int nvg = min(GPB, max(0, valid_g - (chunk + 1) * GPB));
            const float4* wsrc = reinterpret_cast<const float4*>(
                w3 + (size_t)(g0 + (chunk + 1) * GPB) * 12);
            float4* wdst = s_w3 + (buf ^ 1) * (GPB * 3);
            const int nw = nvg * 3;
            for (int i = tid; i < nw; i += BLKG)
                __pipeline_memcpy_async(&wdst[i], &wsrc[i], 16);
            __pipeline_commit();
        }

        // compute: warp w owns gl in [w*8, w*8+8); lane = batch
        const float4* w3b = s_w3 + buf * (GPB * 3);
        #pragma unroll
        for (int gg = 0; gg < 8; gg++) {
            const int gl = w * 8 + gg;
            const int gi = chunk * GPB + gl;

            const int e0 = s_edge[gi * 3 + 0] & (T - 1);
            const int e1 = s_edge[gi * 3 + 1] & (T - 1);
            const int e2 = s_edge[gi * 3 + 2] & (T - 1);

            const uint2 p0 = s_h2[e0 * 32 + lane];
            const uint2 p1 = s_h2[e1 * 32 + lane];
            const uint2 p2 = s_h2[e2 * 32 + lane];

            const float4 q1 = w3b[gl * 3 + 0];
            const float4 q2 = w3b[gl * 3 + 1];
            const float4 q3 = w3b[gl * 3 + 2];

            float2 acc0 = make_float2(s_b3[gi], 0.f);
            float2 acc1 = make_float2(0.f, 0.f);

            acc0 = ffma2(__half22float2(*reinterpret_cast<const __half2*>(&p0.x)),
                         make_float2(q1.x, q1.y), acc0);
            acc1 = ffma2(__half22float2(*reinterpret_cast<const __half2*>(&p0.y)),
                         make_float2(q1.z, q1.w), acc1);
            acc0 = ffma2(__half22float2(*reinterpret_cast<const __half2*>(&p1.x)),
                         make_float2(q2.x, q2.y), acc0);
            acc1 = ffma2(__half22float2(*reinterpret_cast<const __half2*>(&p1.y)),
                         make_float2(q2.z, q2.w), acc1);
            acc0 = ffma2(__half22float2(*reinterpret_cast<const __half2*>(&p2.x)),
                         make_float2(q3.x, q3.y), acc0);
            acc1 = ffma2(__half22float2(*reinterpret_cast<const __half2*>(&p2.y)),
                         make_float2(q3.z, q3.w), acc1);

            const float r = (acc0.x + acc1.x) + (acc0.y + acc1.y);
            s_out[gl * 32 + (lane ^ (gl & 31))] = r;   // conflict-free swizzle
        }
        __syncthreads();

        // coalesced write-out: warp = batch row, lane = consecutive g
        {
            const int gbase = g0 + chunk * GPB;
            float* orow = out + (size_t)(bt * BT + w) * G + gbase;
            #pragma unroll
            for (int it2 = 0; it2 < 8; it2++) {
                const int gl = it2 * 32 + lane;
                if (gbase + gl < G)
                    orow[gl] = s_out[gl * 32 + (w ^ lane)];
            }
        }

        if (has_next) __pipeline_wait_prior(0);
        __syncthreads();   // s_out free; next w3 buffer visible
        buf ^= 1;
    }
}

extern "C" void kernel_launch(void* const* d_in, const int* in_sizes, int n_in,
                              void* d_out, int out_size) {
    const float* features = (const float*)d_in[0];   // [B, T]
    const float* w1       = (const float*)d_in[1];   // [T, K]
    const float* b1       = (const float*)d_in[2];   // [T, K]
    const float* w2       = (const float*)d_in[3];   // [T, K, K]
    const float* b2       = (const float*)d_in[4];   // [T, K]
    const float* w3       = (const float*)d_in[5];   // [G, EPG, K]
    const float* b3       = (const float*)d_in[6];   // [G]
    const int*   edge     = (const int*)  d_in[7];   // [G, EPG]
    float*       out      = (float*)d_out;           // [B, G]

    cudaFuncSetAttribute(fused_kernel,
                         cudaFuncAttributeMaxDynamicSharedMemorySize, SMEM_TOTAL);
    dim3 grid(NSPLIT, NBT);
    fused_kernel<<<grid, BLKG, SMEM_TOTAL>>>(
        features, (const float4*)w1, (const float4*)b1,
        (const float4*)w2, (const float4*)b2,
        w3, b3, edge, out);
}

// round 8
// speedup vs baseline: 1.1150x; 1.1150x over previous
#include <cuda_runtime.h>
#include <cuda_fp16.h>
#include <cuda_pipeline.h>

#define T    512
#define K    4
#define G    20000
#define EPG  3
#define B    512

#define BT     32                  // batches per tile (= lanes)
#define NBT    (B / BT)            // 16
#define BLKG   1024                // 32 warps
#define GPB    256                 // g per chunk
#define NCHUNK 81                  // 81*256 = 20736; 9 splits x 9 chunks
#define GPAD   (NCHUNK * GPB)      // 20736
#define NSPLIT 9                   // grid 16*9 = 144 ~= 1 wave
#define BLKP   512                 // prep threads

// h2 fp16, layout [bt][t][b_in] as uint2 (k0k1, k2k3): 2 MB, L2-resident.
__device__ uint2  g_h2u[NBT * T * BT];
// per-g 16B record: {e0*32, e1*32, e2*32 (int bits), b3}
__device__ float4 g_q0[GPAD];

// SMEM layout (bytes): h2 128K | w3 2x12K | q0 2x4K | out 32K = 192K
#define S_H2   0
#define S_W3   131072
#define S_Q0   (131072 + 24576)
#define S_OUT  (131072 + 24576 + 8192)
#define SMEM_TOTAL (131072 + 24576 + 8192 + 32768)

__device__ __forceinline__ float leaky(float x) {
    return x > 0.0f ? x : 0.01f * x;
}

// Packed f32x2 FMA (Blackwell FFMA2) — bit-identical to two scalar fp32 FMAs.
__device__ __forceinline__ float2 ffma2(float2 a, float2 b, float2 c) {
    float2 d;
    asm("{\n\t"
        ".reg .b64 ra, rb, rc, rd;\n\t"
        "mov.b64 ra, {%2, %3};\n\t"
        "mov.b64 rb, {%4, %5};\n\t"
        "mov.b64 rc, {%6, %7};\n\t"
        "fma.rn.f32x2 rd, ra, rb, rc;\n\t"
        "mov.b64 {%0, %1}, rd;\n\t"
        "}"
        : "=f"(d.x), "=f"(d.y)
        : "f"(a.x), "f"(a.y), "f"(b.x), "f"(b.y), "f"(c.x), "f"(c.y));
    return d;
}

// ---------------------------------------------------------------------------
// Prep: blocks [0,512) compute h2; blocks [512, 512+41) pack q0 records.
// ---------------------------------------------------------------------------
#define H2_BLOCKS   512
#define PACK_BLOCKS ((GPAD + BLKP - 1) / BLKP)   // 41

__global__ void prep_kernel(const float*  __restrict__ features,
                            const float4* __restrict__ w1,
                            const float4* __restrict__ b1,
                            const float4* __restrict__ w2,
                            const float4* __restrict__ b2,
                            const int*    __restrict__ edge,
                            const float*  __restrict__ b3) {
    const int tid = threadIdx.x;
    if (blockIdx.x < H2_BLOCKS) {
        const int b_in = tid & 31;
        const int ty   = tid >> 5;
        const int bt   = blockIdx.x & (NBT - 1);
        const int t    = (blockIdx.x >> 4) * 16 + ty;
        const int b    = bt * BT + b_in;

        const float  f   = features[b * T + t];
        const float4 w1v = w1[t];
        const float4 b1v = b1[t];
        const float4 b2v = b2[t];

        const float h0 = leaky(fmaf(f, w1v.x, b1v.x));
        const float h1 = leaky(fmaf(f, w1v.y, b1v.y));
        const float h2 = leaky(fmaf(f, w1v.z, b1v.z));
        const float h3 = leaky(fmaf(f, w1v.w, b1v.w));

        const float4 w20 = w2[t * 4 + 0];
        const float4 w21 = w2[t * 4 + 1];
        const float4 w22 = w2[t * 4 + 2];
        const float4 w23 = w2[t * 4 + 3];

        float4 o;
        o.x = leaky(fmaf(h3, w23.x, fmaf(h2, w22.x, fmaf(h1, w21.x, fmaf(h0, w20.x, b2v.x)))));
        o.y = leaky(fmaf(h3, w23.y, fmaf(h2, w22.y, fmaf(h1, w21.y, fmaf(h0, w20.y, b2v.y)))));
        o.z = leaky(fmaf(h3, w23.z, fmaf(h2, w22.z, fmaf(h1, w21.z, fmaf(h0, w20.z, b2v.z)))));
        o.w = leaky(fmaf(h3, w23.w, fmaf(h2, w22.w, fmaf(h1, w21.w, fmaf(h0, w20.w, b2v.w)))));

        const __half2 p0 = __floats2half2_rn(o.x, o.y);
        const __half2 p1 = __floats2half2_rn(o.z, o.w);
        uint2 p;
        p.x = *reinterpret_cast<const unsigned int*>(&p0);
        p.y = *reinterpret_cast<const unsigned int*>(&p1);
        g_h2u[((size_t)bt * T + t) * BT + b_in] = p;
    } else {
        const int g = (blockIdx.x - H2_BLOCKS) * BLKP + tid;
        if (g >= GPAD) return;
        float4 q = make_float4(0.f, 0.f, 0.f, 0.f);
        if (g < G) {
            q = make_float4(__int_as_float(edge[3 * g + 0] * BT),
                            __int_as_float(edge[3 * g + 1] * BT),
                            __int_as_float(edge[3 * g + 2] * BT),
                            b3[g]);
        }
        g_q0[g] = q;
    }
}

// ---------------------------------------------------------------------------
// Gather: persistent h2 tile + double-buffered {w3 raw, q0} chunks.
// Warp-private output slices -> single block barrier per chunk.
// ---------------------------------------------------------------------------
__global__ void __launch_bounds__(BLKG, 1)
gather_kernel(const float* __restrict__ w3, float* __restrict__ out) {
    extern __shared__ char sm[];
    uint2*  s_h2 = reinterpret_cast<uint2*>(sm + S_H2);     // [T*BT]
    float4* s_w3 = reinterpret_cast<float4*>(sm + S_W3);    // [2][GPB*3]
    float4* s_q0 = reinterpret_cast<float4*>(sm + S_Q0);    // [2][GPB]
    float*  s_out = reinterpret_cast<float*>(sm + S_OUT);   // [32][8*32]

    const int tid  = threadIdx.x;
    const int bt   = blockIdx.y;
    const int w    = tid >> 5;
    const int lane = tid & 31;

    // Stage persistent h2 tile + first chunk (w3 + q0).
    {
        const uint4* src = reinterpret_cast<const uint4*>(g_h2u + (size_t)bt * T * BT);
        uint4*       dst = reinterpret_cast<uint4*>(s_h2);
        #pragma unroll
        for (int i = tid; i < T * BT / 2; i += BLKG)
            __pipeline_memcpy_async(&dst[i], &src[i], 16);
    }
    int c = blockIdx.x;   // first chunk for this split
    {
        const int nvg = min(GPB, max(0, G - c * GPB));
        const float4* wsrc = reinterpret_cast<const float4*>(w3 + (size_t)c * GPB * 12);
        for (int i = tid; i < nvg * 3; i += BLKG)
            __pipeline_memcpy_async(&s_w3[i], &wsrc[i], 16);
        const float4* qsrc = g_q0 + (size_t)c * GPB;
        if (tid < GPB)
            __pipeline_memcpy_async(&s_q0[tid], &qsrc[tid], 16);
    }
    __pipeline_commit();
    __pipeline_wait_prior(0);
    __syncthreads();

    const uint2* s_h2_lane = s_h2 + lane;
    float* slice = s_out + w * (8 * 32);

    int buf = 0;
    #pragma unroll 1
    for (int iter = 0; iter < NCHUNK / NSPLIT; iter++) {   // 9 chunks/split
        const int  cn       = c + NSPLIT;
        const bool has_next = (iter + 1 < NCHUNK / NSPLIT);

        if (has_next) {
            const int nvg = min(GPB, max(0, G - cn * GPB));
            const float4* wsrc = reinterpret_cast<const float4*>(w3 + (size_t)cn * GPB * 12);
            float4*       wdst = s_w3 + (buf ^ 1) * (GPB * 3);
            for (int i = tid; i < nvg * 3; i += BLKG)
                __pipeline_memcpy_async(&wdst[i], &wsrc[i], 16);
            const float4* qsrc = g_q0 + (size_t)cn * GPB;
            if (tid < GPB)
                __pipeline_memcpy_async(&s_q0[(buf ^ 1) * GPB + tid], &qsrc[tid], 16);
            __pipeline_commit();
        }

        // Compute: warp w owns gl in [w*8, w*8+8), processed in ILP pairs.
        {
            const float4* q0b = s_q0 + buf * GPB;
            const float4* w3b = s_w3 + buf * (GPB * 3);
            const int gl0 = w * 8;

            #pragma unroll
            for (int pp = 0; pp < 4; pp++) {
                const int ga = gl0 + 2 * pp;
                const int gb = ga + 1;

                // Batched loads for the pair (break the q0->h2 serial chain).
                const float4 qa0 = q0b[ga];
                const float4 qb0 = q0b[gb];
                const uint2 pa0 = s_h2_lane[__float_as_int(qa0.x)];
                const uint2 pa1 = s_h2_lane[__float_as_int(qa0.y)];
                const uint2 pa2 = s_h2_lane[__float_as_int(qa0.z)];
                const uint2 pb0 = s_h2_lane[__float_as_int(qb0.x)];
                const uint2 pb1 = s_h2_lane[__float_as_int(qb0.y)];
                const uint2 pb2 = s_h2_lane[__float_as_int(qb0.z)];

                // ---- g a ----
                {
                    const float4 q1 = w3b[ga * 3 + 0];
                    const float4 q2 = w3b[ga * 3 + 1];
                    const float4 q3 = w3b[ga * 3 + 2];
                    float2 acc0 = make_float2(qa0.w, 0.f);
                    float2 acc1 = make_float2(0.f, 0.f);
                    acc0 = ffma2(__half22float2(*reinterpret_cast<const __half2*>(&pa0.x)),
                                 make_float2(q1.x, q1.y), acc0);
                    acc1 = ffma2(__half22float2(*reinterpret_cast<const __half2*>(&pa0.y)),
                                 make_float2(q1.z, q1.w), acc1);
                    acc0 = ffma2(__half22float2(*reinterpret_cast<const __half2*>(&pa1.x)),
                                 make_float2(q2.x, q2.y), acc0);
                    acc1 = ffma2(__half22float2(*reinterpret_cast<const __half2*>(&pa1.y)),
                                 make_float2(q2.z, q2.w), acc1);
                    acc0 = ffma2(__half22float2(*reinterpret_cast<const __half2*>(&pa2.x)),
                                 make_float2(q3.x, q3.y), acc0);
                    acc1 = ffma2(__half22float2(*reinterpret_cast<const __half2*>(&pa2.y)),
                                 make_float2(q3.z, q3.w), acc1);
                    const float r = (acc0.x + acc1.x) + (acc0.y + acc1.y);
                    const int gp = 2 * pp;
                    slice[gp * 32 + ((lane + gp * 4) & 31)] = r;   // rotate swizzle
                }
                // ---- g b ----
                {
                    const float4 q1 = w3b[gb * 3 + 0];
                    const float4 q2 = w3b[gb * 3 + 1];
                    const float4 q3 = w3b[gb * 3 + 2];
                    float2 acc0 = make_float2(qb0.w, 0.f);
                    float2 acc1 = make_float2(0.f, 0.f);
                    acc0 = ffma2(__half22float2(*reinterpret_cast<const __half2*>(&pb0.x)),
                                 make_float2(q1.x, q1.y), acc0);
                    acc1 = ffma2(__half22float2(*reinterpret_cast<const __half2*>(&pb0.y)),
                                 make_float2(q1.z, q1.w), acc1);
                    acc0 = ffma2(__half22float2(*reinterpret_cast<const __half2*>(&pb1.x)),
                                 make_float2(q2.x, q2.y), acc0);
                    acc1 = ffma2(__half22float2(*reinterpret_cast<const __half2*>(&pb1.y)),
                                 make_float2(q2.z, q2.w), acc1);
                    acc0 = ffma2(__half22float2(*reinterpret_cast<const __half2*>(&pb2.x)),
                                 make_float2(q3.x, q3.y), acc0);
                    acc1 = ffma2(__half22float2(*reinterpret_cast<const __half2*>(&pb2.y)),
                                 make_float2(q3.z, q3.w), acc1);
                    const float r = (acc0.x + acc1.x) + (acc0.y + acc1.y);
                    const int gp = 2 * pp + 1;
                    slice[gp * 32 + ((lane + gp * 4) & 31)] = r;
                }
            }
        }
        __syncwarp();

        // Warp-private write-out: 8 iters x (4 b rows x 8 consecutive g).
        {
            const int gbase = c * GPB + w * 8;
            const int gp    = lane & 7;          // g within slice
            const int bs    = lane >> 3;         // 0..3
            if (gbase + gp < G) {
                #pragma unroll
                for (int it = 0; it < 8; it++) {
                    const int b_local = it * 4 + bs;
                    const float v = slice[gp * 32 + ((b_local + gp * 4) & 31)];
                    out[(size_t)(bt * BT + b_local) * G + gbase + gp] = v;
                }
            }
        }

        if (!has_next) break;
        __pipeline_wait_prior(0);
        __syncthreads();   // buf consumed by all; next chunk data visible
        buf ^= 1;
        c = cn;
    }
}

extern "C" void kernel_launch(void* const* d_in, const int* in_sizes, int n_in,
                              void* d_out, int out_size) {
    const float* features = (const float*)d_in[0];   // [B, T]
    const float* w1       = (const float*)d_in[1];   // [T, K]
    const float* b1       = (const float*)d_in[2];   // [T, K]
    const float* w2       = (const float*)d_in[3];   // [T, K, K]
    const float* b2       = (const float*)d_in[4];   // [T, K]
    const float* w3       = (const float*)d_in[5];   // [G, EPG, K]
    const float* b3       = (const float*)d_in[6];   // [G]
    const int*   edge     = (const int*)  d_in[7];   // [G, EPG]
    float*       out      = (float*)d_out;           // [B, G]

    prep_kernel<<<H2_BLOCKS + PACK_BLOCKS, BLKP>>>(
        features, (const float4*)w1, (const float4*)b1,
        (const float4*)w2, (const float4*)b2, edge, b3);

    cudaFuncSetAttribute(gather_kernel,
                         cudaFuncAttributeMaxDynamicSharedMemorySize, SMEM_TOTAL);
    dim3 gridB(NSPLIT, NBT);
    gather_kernel<<<gridB, BLKG, SMEM_TOTAL>>>(w3, out);
}

// round 9
// speedup vs baseline: 1.1757x; 1.0544x over previous
#include <cuda_runtime.h>
#include <cuda_fp16.h>
#include <cuda_pipeline.h>

#define T    512
#define K    4
#define G    20000
#define EPG  3
#define B    512

#define BT     32                  // batches per tile (= lanes)
#define NBT    (B / BT)            // 16
#define BLKG   1024                // 32 warps
#define GPB    256                 // g per chunk
#define CPS    9                   // chunks per split
#define NCHUNK 81                  // 81*256 = 20736; 9 splits x 9 chunks
#define GPAD   (NCHUNK * GPB)      // 20736
#define NSPLIT 9                   // grid 16*9 = 144 ~= 1 wave
#define BLKP   512                 // prep threads

// h2 fp16, layout [bt][t][b_in] as uint2 (k0k1, k2k3): 2 MB, L2-resident.
__device__ uint2  g_h2u[NBT * T * BT];
// per-g 16B record: {e0*32, e1*32, e2*32 (int bits), b3}
__device__ float4 g_q0[GPAD];

// SMEM layout (bytes): h2 128K | w3 2x12K | q0 2x4K | out 2x32K = 224K
#define S_H2   0
#define S_W3   131072
#define S_Q0   (131072 + 24576)
#define S_OUT  (131072 + 24576 + 8192)
#define SMEM_TOTAL (131072 + 24576 + 8192 + 65536)

__device__ __forceinline__ float leaky(float x) {
    return x > 0.0f ? x : 0.01f * x;
}

// Packed f32x2 FMA (Blackwell FFMA2) — bit-identical to two scalar fp32 FMAs.
__device__ __forceinline__ float2 ffma2(float2 a, float2 b, float2 c) {
    float2 d;
    asm("{\n\t"
        ".reg .b64 ra, rb, rc, rd;\n\t"
        "mov.b64 ra, {%2, %3};\n\t"
        "mov.b64 rb, {%4, %5};\n\t"
        "mov.b64 rc, {%6, %7};\n\t"
        "fma.rn.f32x2 rd, ra, rb, rc;\n\t"
        "mov.b64 {%0, %1}, rd;\n\t"
        "}"
        : "=f"(d.x), "=f"(d.y)
        : "f"(a.x), "f"(a.y), "f"(b.x), "f"(b.y), "f"(c.x), "f"(c.y));
    return d;
}

// ---------------------------------------------------------------------------
// Prep: blocks [0,512) compute h2; blocks [512, 512+41) pack q0 records.
// ---------------------------------------------------------------------------
#define H2_BLOCKS   512
#define PACK_BLOCKS ((GPAD + BLKP - 1) / BLKP)   // 41

__global__ void prep_kernel(const float*  __restrict__ features,
                            const float4* __restrict__ w1,
                            const float4* __restrict__ b1,
                            const float4* __restrict__ w2,
                            const float4* __restrict__ b2,
                            const int*    __restrict__ edge,
                            const float*  __restrict__ b3) {
    const int tid = threadIdx.x;
    if (blockIdx.x < H2_BLOCKS) {
        const int b_in = tid & 31;
        const int ty   = tid >> 5;
        const int bt   = blockIdx.x & (NBT - 1);
        const int t    = (blockIdx.x >> 4) * 16 + ty;
        const int b    = bt * BT + b_in;

        const float  f   = features[b * T + t];
        const float4 w1v = w1[t];
        const float4 b1v = b1[t];
        const float4 b2v = b2[t];

        const float h0 = leaky(fmaf(f, w1v.x, b1v.x));
        const float h1 = leaky(fmaf(f, w1v.y, b1v.y));
        const float h2 = leaky(fmaf(f, w1v.z, b1v.z));
        const float h3 = leaky(fmaf(f, w1v.w, b1v.w));

        const float4 w20 = w2[t * 4 + 0];
        const float4 w21 = w2[t * 4 + 1];
        const float4 w22 = w2[t * 4 + 2];
        const float4 w23 = w2[t * 4 + 3];

        float4 o;
        o.x = leaky(fmaf(h3, w23.x, fmaf(h2, w22.x, fmaf(h1, w21.x, fmaf(h0, w20.x, b2v.x)))));
        o.y = leaky(fmaf(h3, w23.y, fmaf(h2, w22.y, fmaf(h1, w21.y, fmaf(h0, w20.y, b2v.y)))));
        o.z = leaky(fmaf(h3, w23.z, fmaf(h2, w22.z, fmaf(h1, w21.z, fmaf(h0, w20.z, b2v.z)))));
        o.w = leaky(fmaf(h3, w23.w, fmaf(h2, w22.w, fmaf(h1, w21.w, fmaf(h0, w20.w, b2v.w)))));

        const __half2 p0 = __floats2half2_rn(o.x, o.y);
        const __half2 p1 = __floats2half2_rn(o.z, o.w);
        uint2 p;
        p.x = *reinterpret_cast<const unsigned int*>(&p0);
        p.y = *reinterpret_cast<const unsigned int*>(&p1);
        g_h2u[((size_t)bt * T + t) * BT + b_in] = p;
    } else {
        const int g = (blockIdx.x - H2_BLOCKS) * BLKP + tid;
        if (g >= GPAD) return;
        float4 q = make_float4(0.f, 0.f, 0.f, 0.f);
        if (g < G) {
            q = make_float4(__int_as_float(edge[3 * g + 0] * BT),
                            __int_as_float(edge[3 * g + 1] * BT),
                            __int_as_float(edge[3 * g + 2] * BT),
                            b3[g]);
        }
        g_q0[g] = q;
    }
}

// ---------------------------------------------------------------------------
// Gather: persistent h2 tile, double-buffered {w3, q0, s_out}.
// ONE block barrier per chunk; writeout(i) overlaps compute(i+1) via s_out[2].
// ---------------------------------------------------------------------------
__global__ void __launch_bounds__(BLKG, 1)
gather_kernel(const float* __restrict__ w3, float* __restrict__ out) {
    extern __shared__ char sm[];
    uint2*  s_h2  = reinterpret_cast<uint2*>(sm + S_H2);     // [T*BT]
    float4* s_w3  = reinterpret_cast<float4*>(sm + S_W3);    // [2][GPB*3]
    float4* s_q0  = reinterpret_cast<float4*>(sm + S_Q0);    // [2][GPB]
    float*  s_out = reinterpret_cast<float*>(sm + S_OUT);    // [2][GPB*32]

    const int tid  = threadIdx.x;
    const int bt   = blockIdx.y;
    const int w    = tid >> 5;
    const int lane = tid & 31;

    // Stage persistent h2 tile + first chunk (w3 + q0).
    {
        const uint4* src = reinterpret_cast<const uint4*>(g_h2u + (size_t)bt * T * BT);
        uint4*       dst = reinterpret_cast<uint4*>(s_h2);
        #pragma unroll
        for (int i = tid; i < T * BT / 2; i += BLKG)
            __pipeline_memcpy_async(&dst[i], &src[i], 16);
    }
    int c = blockIdx.x;   // first chunk for this split
    {
        const int nvg = min(GPB, max(0, G - c * GPB));
        const float4* wsrc = reinterpret_cast<const float4*>(w3 + (size_t)c * GPB * 12);
        for (int i = tid; i < nvg * 3; i += BLKG)
            __pipeline_memcpy_async(&s_w3[i], &wsrc[i], 16);
        const float4* qsrc = g_q0 + (size_t)c * GPB;
        if (tid < GPB)
            __pipeline_memcpy_async(&s_q0[tid], &qsrc[tid], 16);
    }
    __pipeline_commit();
    __pipeline_wait_prior(0);
    __syncthreads();

    const uint2* s_h2_lane = s_h2 + lane;

    #pragma unroll 1
    for (int iter = 0; iter < CPS; iter++) {
        const int  buf      = iter & 1;
        const bool has_next = (iter + 1 < CPS);

        // Prefetch next chunk into the other buffers (overlaps compute below).
        if (has_next) {
            const int cn  = c + NSPLIT;
            const int nvg = min(GPB, max(0, G - cn * GPB));
            const float4* wsrc = reinterpret_cast<const float4*>(w3 + (size_t)cn * GPB * 12);
            float4*       wdst = s_w3 + (buf ^ 1) * (GPB * 3);
            for (int i = tid; i < nvg * 3; i += BLKG)
                __pipeline_memcpy_async(&wdst[i], &wsrc[i], 16);
            const float4* qsrc = g_q0 + (size_t)cn * GPB;
            if (tid < GPB)
                __pipeline_memcpy_async(&s_q0[(buf ^ 1) * GPB + tid], &qsrc[tid], 16);
            __pipeline_commit();
        }

        // Compute: warp w owns gl in [w*8, w*8+8), processed in ILP pairs.
        {
            const float4* q0b = s_q0 + buf * GPB;
            const float4* w3b = s_w3 + buf * (GPB * 3);
            float*        ob  = s_out + buf * (GPB * 32);
            const int gl0 = w * 8;

            #pragma unroll
            for (int pp = 0; pp < 4; pp++) {
                const int ga = gl0 + 2 * pp;
                const int gb = ga + 1;

                const float4 qa0 = q0b[ga];
                const float4 qb0 = q0b[gb];
                const uint2 pa0 = s_h2_lane[__float_as_int(qa0.x)];
                const uint2 pa1 = s_h2_lane[__float_as_int(qa0.y)];
                const uint2 pa2 = s_h2_lane[__float_as_int(qa0.z)];
                const uint2 pb0 = s_h2_lane[__float_as_int(qb0.x)];
                const uint2 pb1 = s_h2_lane[__float_as_int(qb0.y)];
                const uint2 pb2 = s_h2_lane[__float_as_int(qb0.z)];

                {
                    const float4 q1 = w3b[ga * 3 + 0];
                    const float4 q2 = w3b[ga * 3 + 1];
                    const float4 q3 = w3b[ga * 3 + 2];
                    float2 acc0 = make_float2(qa0.w, 0.f);
                    float2 acc1 = make_float2(0.f, 0.f);
                    acc0 = ffma2(__half22float2(*reinterpret_cast<const __half2*>(&pa0.x)),
                                 make_float2(q1.x, q1.y), acc0);
                    acc1 = ffma2(__half22float2(*reinterpret_cast<const __half2*>(&pa0.y)),
                                 make_float2(q1.z, q1.w), acc1);
                    acc0 = ffma2(__half22float2(*reinterpret_cast<const __half2*>(&pa1.x)),
                                 make_float2(q2.x, q2.y), acc0);
                    acc1 = ffma2(__half22float2(*reinterpret_cast<const __half2*>(&pa1.y)),
                                 make_float2(q2.z, q2.w), acc1);
                    acc0 = ffma2(__half22float2(*reinterpret_cast<const __half2*>(&pa2.x)),
                                 make_float2(q3.x, q3.y), acc0);
                    acc1 = ffma2(__half22float2(*reinterpret_cast<const __half2*>(&pa2.y)),
                                 make_float2(q3.z, q3.w), acc1);
                    const float r = (acc0.x + acc1.x) + (acc0.y + acc1.y);
                    ob[ga * 32 + (lane ^ (ga & 31))] = r;   // conflict-free swizzle
                }
                {
                    const float4 q1 = w3b[gb * 3 + 0];
                    const float4 q2 = w3b[gb * 3 + 1];
                    const float4 q3 = w3b[gb * 3 + 2];
                    float2 acc0 = make_float2(qb0.w, 0.f);
                    float2 acc1 = make_float2(0.f, 0.f);
                    acc0 = ffma2(__half22float2(*reinterpret_cast<const __half2*>(&pb0.x)),
                                 make_float2(q1.x, q1.y), acc0);
                    acc1 = ffma2(__half22float2(*reinterpret_cast<const __half2*>(&pb0.y)),
                                 make_float2(q1.z, q1.w), acc1);
                    acc0 = ffma2(__half22float2(*reinterpret_cast<const __half2*>(&pb1.x)),
                                 make_float2(q2.x, q2.y), acc0);
                    acc1 = ffma2(__half22float2(*reinterpret_cast<const __half2*>(&pb1.y)),
                                 make_float2(q2.z, q2.w), acc1);
                    acc0 = ffma2(__half22float2(*reinterpret_cast<const __half2*>(&pb2.x)),
                                 make_float2(q3.x, q3.y), acc0);
                    acc1 = ffma2(__half22float2(*reinterpret_cast<const __half2*>(&pb2.y)),
                                 make_float2(q3.z, q3.w), acc1);
                    const float r = (acc0.x + acc1.x) + (acc0.y + acc1.y);
                    ob[gb * 32 + (lane ^ (gb & 31))] = r;
                }
            }
        }

        // ONE barrier: publishes s_out[buf] to all warps. The next iteration's
        // compute writes s_out[buf^1], so no second barrier is required; a warp
        // can only reach the NEXT barrier after finishing this writeout.
        __syncthreads();

        // Coalesced write-out: warp = batch row, lane = consecutive g (128B STG).
        {
            const float* ob = s_out + buf * (GPB * 32);
            const int gbase = c * GPB;
            float* orow = out + (size_t)(bt * BT + w) * G + gbase;
            #pragma unroll
            for (int it2 = 0; it2 < 8; it2++) {
                const int gl = it2 * 32 + lane;
                if (gbase + gl < G)
                    orow[gl] = ob[gl * 32 + (w ^ lane)];
            }
        }

        if (has_next) __pipeline_wait_prior(0);   // next w3/q0 resident
        c += NSPLIT;
    }
}

extern "C" void kernel_launch(void* const* d_in, const int* in_sizes, int n_in,
                              void* d_out, int out_size) {
    const float* features = (const float*)d_in[0];   // [B, T]
    const float* w1       = (const float*)d_in[1];   // [T, K]
    const float* b1       = (const float*)d_in[2];   // [T, K]
    const float* w2       = (const float*)d_in[3];   // [T, K, K]
    const float* b2       = (const float*)d_in[4];   // [T, K]
    const float* w3       = (const float*)d_in[5];   // [G, EPG, K]
    const float* b3       = (const float*)d_in[6];   // [G]
    const int*   edge     = (const int*)  d_in[7];   // [G, EPG]
    float*       out      = (float*)d_out;           // [B, G]

    prep_kernel<<<H2_BLOCKS + PACK_BLOCKS, BLKP>>>(
        features, (const float4*)w1, (const float4*)b1,
        (const float4*)w2, (const float4*)b2, edge, b3);

    cudaFuncSetAttribute(gather_kernel,
                         cudaFuncAttributeMaxDynamicSharedMemorySize, SMEM_TOTAL);
    dim3 gridB(NSPLIT, NBT);
    gather_kernel<<<gridB, BLKG, SMEM_TOTAL>>>(w3, out);
}

// round 10
// speedup vs baseline: 1.2613x; 1.0727x over previous
#include <cuda_runtime.h>
#include <cuda_fp16.h>
#include <cuda_pipeline.h>

#define T    512
#define K    4
#define G    20000
#define EPG  3
#define B    512

#define BT     32                  // batches per tile (= lanes)
#define NBT    (B / BT)            // 16
#define BLKG   1024                // 32 warps
#define GPB    256                 // g per chunk
#define CPS    9                   // chunks per split
#define NCHUNK 81                  // 81*256 = 20736; 9 splits x 9 chunks
#define GPAD   (NCHUNK * GPB)      // 20736
#define NSPLIT 9                   // grid 16*9 = 144 ~= 1 wave
#define BLKP   512                 // prep threads

// h2 fp16, layout [bt][t][b_in] as uint2 (k0k1, k2k3): 2 MB, L2-resident.
__device__ uint2  g_h2u[NBT * T * BT];
// per-g 16B record: {e0*32, e1*32, e2*32 (int bits), b3}
__device__ float4 g_q0[GPAD];

// SMEM (bytes): h2 128K | rec 2x16K (64B/g interleaved) | out 2x32K = 224K
#define S_H2   0
#define S_REC  131072
#define S_OUT  (131072 + 32768)
#define SMEM_TOTAL (131072 + 32768 + 65536)

__device__ __forceinline__ float leaky(float x) {
    return x > 0.0f ? x : 0.01f * x;
}

// Packed f32x2 FMA (Blackwell FFMA2) — bit-identical to two scalar fp32 FMAs.
__device__ __forceinline__ float2 ffma2(float2 a, float2 b, float2 c) {
    float2 d;
    asm("{\n\t"
        ".reg .b64 ra, rb, rc, rd;\n\t"
        "mov.b64 ra, {%2, %3};\n\t"
        "mov.b64 rb, {%4, %5};\n\t"
        "mov.b64 rc, {%6, %7};\n\t"
        "fma.rn.f32x2 rd, ra, rb, rc;\n\t"
        "mov.b64 {%0, %1}, rd;\n\t"
        "}"
        : "=f"(d.x), "=f"(d.y)
        : "f"(a.x), "f"(a.y), "f"(b.x), "f"(b.y), "f"(c.x), "f"(c.y));
    return d;
}

// ---------------------------------------------------------------------------
// Prep: blocks [0,512) compute h2; blocks [512, 512+41) pack q0 records.
// ---------------------------------------------------------------------------
#define H2_BLOCKS   512
#define PACK_BLOCKS ((GPAD + BLKP - 1) / BLKP)   // 41

__global__ void prep_kernel(const float*  __restrict__ features,
                            const float4* __restrict__ w1,
                            const float4* __restrict__ b1,
                            const float4* __restrict__ w2,
                            const float4* __restrict__ b2,
                            const int*    __restrict__ edge,
                            const float*  __restrict__ b3) {
    const int tid = threadIdx.x;
    if (blockIdx.x < H2_BLOCKS) {
        const int b_in = tid & 31;
        const int ty   = tid >> 5;
        const int bt   = blockIdx.x & (NBT - 1);
        const int t    = (blockIdx.x >> 4) * 16 + ty;
        const int b    = bt * BT + b_in;

        const float  f   = features[b * T + t];
        const float4 w1v = w1[t];
        const float4 b1v = b1[t];
        const float4 b2v = b2[t];

        const float h0 = leaky(fmaf(f, w1v.x, b1v.x));
        const float h1 = leaky(fmaf(f, w1v.y, b1v.y));
        const float h2 = leaky(fmaf(f, w1v.z, b1v.z));
        const float h3 = leaky(fmaf(f, w1v.w, b1v.w));

        const float4 w20 = w2[t * 4 + 0];
        const float4 w21 = w2[t * 4 + 1];
        const float4 w22 = w2[t * 4 + 2];
        const float4 w23 = w2[t * 4 + 3];

        float4 o;
        o.x = leaky(fmaf(h3, w23.x, fmaf(h2, w22.x, fmaf(h1, w21.x, fmaf(h0, w20.x, b2v.x)))));
        o.y = leaky(fmaf(h3, w23.y, fmaf(h2, w22.y, fmaf(h1, w21.y, fmaf(h0, w20.y, b2v.y)))));
        o.z = leaky(fmaf(h3, w23.z, fmaf(h2, w22.z, fmaf(h1, w21.z, fmaf(h0, w20.z, b2v.z)))));
        o.w = leaky(fmaf(h3, w23.w, fmaf(h2, w22.w, fmaf(h1, w21.w, fmaf(h0, w20.w, b2v.w)))));

        const __half2 p0 = __floats2half2_rn(o.x, o.y);
        const __half2 p1 = __floats2half2_rn(o.z, o.w);
        uint2 p;
        p.x = *reinterpret_cast<const unsigned int*>(&p0);
        p.y = *reinterpret_cast<const unsigned int*>(&p1);
        g_h2u[((size_t)bt * T + t) * BT + b_in] = p;
    } else {
        const int g = (blockIdx.x - H2_BLOCKS) * BLKP + tid;
        if (g >= GPAD) return;
        float4 q = make_float4(0.f, 0.f, 0.f, 0.f);
        if (g < G) {
            q = make_float4(__int_as_float(edge[3 * g + 0] * BT),
                            __int_as_float(edge[3 * g + 1] * BT),
                            __int_as_float(edge[3 * g + 2] * BT),
                            b3[g]);
        }
        g_q0[g] = q;
    }
}

// Stage one chunk's w3 into interleaved record slots rec[g*4 + 1..3].
__device__ __forceinline__ void stage_w3(float4* rec, const float* w3,
                                         int c, int tid) {
    const int nvg = min(GPB, max(0, G - c * GPB));
    const float4* wsrc = reinterpret_cast<const float4*>(w3 + (size_t)c * GPB * 12);
    if (tid < GPB * 3) {
        if (tid < nvg * 3) {
            const int g = tid / 3, part = tid - g * 3;
            __pipeline_memcpy_async(&rec[g * 4 + 1 + part], &wsrc[tid], 16);
        }
    }
}
// Stage one chunk's q0 into rec[g*4 + 0].
__device__ __forceinline__ void stage_q0(float4* rec, int c, int tid) {
    const int nvg = min(GPB, max(0, G - c * GPB));
    if (tid >= GPB * 3 && tid < GPB * 3 + GPB) {
        const int g = tid - GPB * 3;
        if (g < nvg)
            __pipeline_memcpy_async(&rec[g * 4], &g_q0[(size_t)c * GPB + g], 16);
    }
}

// ---------------------------------------------------------------------------
// Gather: persistent h2 tile, half-warp g-pairing (1 broadcast wf serves 2 g),
// double-buffered {rec, s_out}, one block barrier per chunk, PDL prologue.
// ---------------------------------------------------------------------------
__global__ void __launch_bounds__(BLKG, 1)
gather_kernel(const float* __restrict__ w3, float* __restrict__ out) {
    extern __shared__ char sm[];
    uint2*  s_h2  = reinterpret_cast<uint2*>(sm + S_H2);     // [T*BT]
    float4* s_rec = reinterpret_cast<float4*>(sm + S_REC);   // [2][GPB*4]
    float*  s_out = reinterpret_cast<float*>(sm + S_OUT);    // [2][GPB*32]

    const int tid  = threadIdx.x;
    const int bt   = blockIdx.y;
    const int w    = tid >> 5;
    const int lane = tid & 31;
    const int half = lane >> 4;     // 0 or 1: which g of the pair
    const int hb   = lane & 15;     // batch within half

    int c = blockIdx.x;   // first chunk for this split

    // PDL: w3 is a kernel input (independent of prep) — stage it while prep runs.
    stage_w3(s_rec, w3, c, tid);
    __pipeline_commit();

    cudaGridDependencySynchronize();   // wait for prep grid (h2 + q0 ready)

    // Stage persistent h2 tile + first chunk's q0.
    {
        const uint4* src = reinterpret_cast<const uint4*>(g_h2u + (size_t)bt * T * BT);
        uint4*       dst = reinterpret_cast<uint4*>(s_h2);
        #pragma unroll
        for (int i = tid; i < T * BT / 2; i += BLKG)
            __pipeline_memcpy_async(&dst[i], &src[i], 16);
    }
    stage_q0(s_rec, c, tid);
    __pipeline_commit();
    __pipeline_wait_prior(0);
    __syncthreads();

    const int rotl = ((lane & 1) << 4) | ((lane >> 1) & 15);   // writeout swizzle

    #pragma unroll 1
    for (int iter = 0; iter < CPS; iter++) {
        const int  buf      = iter & 1;
        const bool has_next = (iter + 1 < CPS);

        // Prefetch next chunk into the other buffer (overlaps compute below).
        if (has_next) {
            const int cn = c + NSPLIT;
            float4* rdst = s_rec + (buf ^ 1) * (GPB * 4);
            stage_w3(rdst, w3, cn, tid);
            stage_q0(rdst, cn, tid);
            __pipeline_commit();
        }

        // Compute: warp w owns 8 g as 4 half-warp pairs; 2 passes over batches.
        {
            const float4* rec = s_rec + buf * (GPB * 4);
            float*        ob  = s_out + buf * (GPB * 32);
            const int gl0 = w * 8;

            #pragma unroll
            for (int pp = 0; pp < 4; pp++) {
                const int gsel = gl0 + 2 * pp + half;

                // One LDS.128 wavefront serves both halves (banks disjoint).
                const float4 q0 = rec[gsel * 4 + 0];
                const float4 q1 = rec[gsel * 4 + 1];
                const float4 q2 = rec[gsel * 4 + 2];
                const float4 q3 = rec[gsel * 4 + 3];

                const int i0 = __float_as_int(q0.x);
                const int i1 = __float_as_int(q0.y);
                const int i2 = __float_as_int(q0.z);
                const int rot = ((gsel & 1) << 4) | ((gsel >> 1) & 15);

                #pragma unroll
                for (int p = 0; p < 2; p++) {
                    const int b = hb + (p << 4);
                    const uint2 p0 = s_h2[i0 + b];
                    const uint2 p1 = s_h2[i1 + b];
                    const uint2 p2 = s_h2[i2 + b];

                    float2 acc0 = make_float2(q0.w, 0.f);
                    float2 acc1 = make_float2(0.f, 0.f);
                    acc0 = ffma2(__half22float2(*reinterpret_cast<const __half2*>(&p0.x)),
                                 make_float2(q1.x, q1.y), acc0);
                    acc1 = ffma2(__half22float2(*reinterpret_cast<const __half2*>(&p0.y)),
                                 make_float2(q1.z, q1.w), acc1);
                    acc0 = ffma2(__half22float2(*reinterpret_cast<const __half2*>(&p1.x)),
                                 make_float2(q2.x, q2.y), acc0);
                    acc1 = ffma2(__half22float2(*reinterpret_cast<const __half2*>(&p1.y)),
                                 make_float2(q2.z, q2.w), acc1);
                    acc0 = ffma2(__half22float2(*reinterpret_cast<const __half2*>(&p2.x)),
                                 make_float2(q3.x, q3.y), acc0);
                    acc1 = ffma2(__half22float2(*reinterpret_cast<const __half2*>(&p2.y)),
                                 make_float2(q3.z, q3.w), acc1);
                    const float r = (acc0.x + acc1.x) + (acc0.y + acc1.y);

                    // bit4 of rot differs between halves -> bank sets disjoint.
                    ob[gsel * 32 + (b ^ rot)] = r;
                }
            }
        }

        // ONE barrier: publishes s_out[buf]; next compute uses s_out[buf^1].
        __syncthreads();

        // Coalesced write-out: warp = batch row, lane = consecutive g (128B STG).
        {
            const float* ob = s_out + buf * (GPB * 32);
            const int gbase = c * GPB;
            float* orow = out + (size_t)(bt * BT + w) * G + gbase;
            #pragma unroll
            for (int it2 = 0; it2 < 8; it2++) {
                const int gl = it2 * 32 + lane;
                if (gbase + gl < G)
                    orow[gl] = ob[gl * 32 + (w ^ rotl)];
            }
        }

        if (has_next) __pipeline_wait_prior(0);   // next rec resident
        c += NSPLIT;
    }
}

extern "C" void kernel_launch(void* const* d_in, const int* in_sizes, int n_in,
                              void* d_out, int out_size) {
    const float* features = (const float*)d_in[0];   // [B, T]
    const float* w1       = (const float*)d_in[1];   // [T, K]
    const float* b1       = (const float*)d_in[2];   // [T, K]
    const float* w2       = (const float*)d_in[3];   // [T, K, K]
    const float* b2       = (const float*)d_in[4];   // [T, K]
    const float* w3       = (const float*)d_in[5];   // [G, EPG, K]
    const float* b3       = (const float*)d_in[6];   // [G]
    const int*   edge     = (const int*)  d_in[7];   // [G, EPG]
    float*       out      = (float*)d_out;           // [B, G]

    prep_kernel<<<H2_BLOCKS + PACK_BLOCKS, BLKP>>>(
        features, (const float4*)w1, (const float4*)b1,
        (const float4*)w2, (const float4*)b2, edge, b3);

    cudaFuncSetAttribute(gather_kernel,
                         cudaFuncAttributeMaxDynamicSharedMemorySize, SMEM_TOTAL);

    // PDL launch: gather may start while prep drains; it syncs on the grid
    // dependency before touching prep's outputs.
    cudaLaunchConfig_t cfg = {};
    cfg.gridDim = dim3(NSPLIT, NBT);
    cfg.blockDim = dim3(BLKG);
    cfg.dynamicSmemBytes = SMEM_TOTAL;
    cudaLaunchAttribute attrs[1];
    attrs[0].id = cudaLaunchAttributeProgrammaticStreamSerialization;
    attrs[0].val.programmaticStreamSerializationAllowed = 1;
    cfg.attrs = attrs;
    cfg.numAttrs = 1;
    cudaLaunchKernelEx(&cfg, gather_kernel, w3, out);
}